// round 1
// baseline (speedup 1.0000x reference)
#include <cuda_runtime.h>

#define DIM     128
#define OUTD    64
#define BM      128
#define BC      32
#define NSPLIT  37
#define THREADS 256

#define FPITCH  132   // padded float stride for sF / sT
#define KPITCH  33    // padded stride for sKd (in ulonglong units)

// smem byte offsets (all 16B aligned)
#define OFF_KD  0
#define OFF_F   33792     // 128*33*8
#define OFF_T   101376    // OFF_F + 128*132*4
#define OFF_W   118272    // OFF_T + 32*132*4
#define OFF_X2  126464    // OFF_W + 32*64*4
#define OFF_T2  126976
#define SMEM_TOTAL 127104

__device__ __forceinline__ void fma2(unsigned long long &acc,
                                     unsigned long long a,
                                     unsigned long long b) {
    asm("fma.rn.f32x2 %0, %1, %2, %0;" : "+l"(acc) : "l"(a), "l"(b));
}

__device__ __forceinline__ unsigned long long pack2(float v) {
    unsigned long long u;
    asm("mov.b64 %0, {%1, %1};" : "=l"(u) : "f"(v));
    return u;
}

__global__ void zero_kernel(float* p, int n) {
    int i = blockIdx.x * blockDim.x + threadIdx.x;
    if (i < n) p[i] = 0.0f;
}

__global__ void __launch_bounds__(THREADS, 1)
rbf_fused_kernel(const float* __restrict__ features,
                 const float* __restrict__ train,
                 const float* __restrict__ weights,
                 float* __restrict__ out,
                 int N, int nChunks, int chunksPerSplit)
{
    extern __shared__ unsigned char smraw[];
    unsigned long long* sKd = (unsigned long long*)(smraw + OFF_KD);
    float* sF  = (float*)(smraw + OFF_F);
    float* sT  = (float*)(smraw + OFF_T);
    float* sW  = (float*)(smraw + OFF_W);
    float* sX2 = (float*)(smraw + OFF_X2);
    float* sT2 = (float*)(smraw + OFF_T2);

    const int t = threadIdx.x;
    const int rowBase = blockIdx.x * BM;

    // ---- load features tile [128 x 128] (once per block) ----
    #pragma unroll
    for (int i = 0; i < 16; i++) {
        int f  = t + i * THREADS;           // float4 index 0..4095
        int r  = f >> 5;
        int c4 = f & 31;
        float4 v = *(const float4*)(features + (size_t)(rowBase + r) * DIM + c4 * 4);
        *(float4*)(sF + r * FPITCH + c4 * 4) = v;
    }
    __syncthreads();

    if (t < BM) {
        float s = 0.0f;
        const float* fr = sF + t * FPITCH;
        #pragma unroll
        for (int k = 0; k < DIM; k++) s += fr[k] * fr[k];
        sX2[t] = s;
    }

    const int ty  = t >> 3;       // 0..31
    const int tx  = t & 7;        // 0..7
    const int r0  = ty * 4;       // 4 rows per thread
    const int cc0 = tx * 4;       // 4 chunk-cols per thread (phase A)
    const int oo0 = tx * 8;       // 8 out-cols per thread (phase B)

    const float NEGINV = -1.0f / (2.0f * 10.077141124806595f);

    unsigned long long acc2[4][4]; // [row][out-col-pair]
    #pragma unroll
    for (int i = 0; i < 4; i++)
        #pragma unroll
        for (int j = 0; j < 4; j++) acc2[i][j] = 0ull;

    const int chunk0 = blockIdx.y * chunksPerSplit;
    const int chunk1 = min(chunk0 + chunksPerSplit, nChunks);

    for (int ch = chunk0; ch < chunk1; ch++) {
        const int c0 = ch * BC;

        __syncthreads();  // protect sT/sW from prior-iteration readers

        // ---- load train chunk [32 x 128] ----
        #pragma unroll
        for (int i = 0; i < 4; i++) {
            int f  = t + i * THREADS;       // float4 index 0..1023
            int r  = f >> 5;
            int c4 = f & 31;
            int gr = c0 + r;
            float4 v = (gr < N)
                ? *(const float4*)(train + (size_t)gr * DIM + c4 * 4)
                : make_float4(0.f, 0.f, 0.f, 0.f);
            *(float4*)(sT + r * FPITCH + c4 * 4) = v;
        }
        // ---- load weights chunk [32 x 64] ----
        #pragma unroll
        for (int i = 0; i < 2; i++) {
            int f  = t + i * THREADS;       // float4 index 0..511
            int r  = f >> 4;
            int c4 = f & 15;
            int gr = c0 + r;
            float4 v = (gr < N)
                ? *(const float4*)(weights + (size_t)gr * OUTD + c4 * 4)
                : make_float4(0.f, 0.f, 0.f, 0.f);
            *(float4*)(sW + r * OUTD + c4 * 4) = v;
        }
        __syncthreads();

        if (t < BC) {
            float s = 0.0f;
            const float* tr = sT + t * FPITCH;
            #pragma unroll
            for (int k = 0; k < DIM; k++) s += tr[k] * tr[k];
            sT2[t] = s;
        }
        __syncthreads();

        // ---- Phase A: S[128,32] = F . T^T  (packed f32x2 over k) ----
        unsigned long long accA[4][4];
        #pragma unroll
        for (int i = 0; i < 4; i++)
            #pragma unroll
            for (int j = 0; j < 4; j++) accA[i][j] = 0ull;

        #pragma unroll 4
        for (int k4 = 0; k4 < 32; k4++) {
            ulonglong2 a[4], b[4];
            #pragma unroll
            for (int i = 0; i < 4; i++)
                a[i] = *(const ulonglong2*)(sF + (r0 + i) * FPITCH + k4 * 4);
            #pragma unroll
            for (int j = 0; j < 4; j++)
                b[j] = *(const ulonglong2*)(sT + (cc0 + j) * FPITCH + k4 * 4);
            #pragma unroll
            for (int i = 0; i < 4; i++)
                #pragma unroll
                for (int j = 0; j < 4; j++) {
                    fma2(accA[i][j], a[i].x, b[j].x);
                    fma2(accA[i][j], a[i].y, b[j].y);
                }
        }

        // ---- RBF epilogue: k = exp(-sqrt(max(d2,0)) / (2*c)) ----
        #pragma unroll
        for (int i = 0; i < 4; i++) {
            float x2 = sX2[r0 + i];
            #pragma unroll
            for (int j = 0; j < 4; j++) {
                float2 p = *(float2*)&accA[i][j];
                float dot = p.x + p.y;
                float d2  = x2 + sT2[cc0 + j] - 2.0f * dot;
                float m   = fmaxf(d2, 0.0f);
                float dist = sqrtf(m);
                float kv  = __expf(dist * NEGINV);
                sKd[(r0 + i) * KPITCH + (cc0 + j)] = pack2(kv);
            }
        }
        __syncthreads();

        // ---- Phase B: acc2 += K[128,32] @ W[32,64] (f32x2 over out cols) ----
        #pragma unroll 8
        for (int c = 0; c < BC; c++) {
            unsigned long long kp[4];
            #pragma unroll
            for (int i = 0; i < 4; i++)
                kp[i] = sKd[(r0 + i) * KPITCH + c];
            ulonglong2 w01 = *(const ulonglong2*)(sW + c * OUTD + oo0);
            ulonglong2 w23 = *(const ulonglong2*)(sW + c * OUTD + oo0 + 4);
            #pragma unroll
            for (int i = 0; i < 4; i++) {
                fma2(acc2[i][0], kp[i], w01.x);
                fma2(acc2[i][1], kp[i], w01.y);
                fma2(acc2[i][2], kp[i], w23.x);
                fma2(acc2[i][3], kp[i], w23.y);
            }
        }
    }

    // ---- reduce across N-splits ----
    #pragma unroll
    for (int i = 0; i < 4; i++) {
        int gr = rowBase + r0 + i;
        #pragma unroll
        for (int j = 0; j < 4; j++) {
            float2 v = *(float2*)&acc2[i][j];
            atomicAdd(out + (size_t)gr * OUTD + oo0 + 2 * j,     v.x);
            atomicAdd(out + (size_t)gr * OUTD + oo0 + 2 * j + 1, v.y);
        }
    }
}

extern "C" void kernel_launch(void* const* d_in, const int* in_sizes, int n_in,
                              void* d_out, int out_size) {
    const float* features = (const float*)d_in[0];
    const float* train    = (const float*)d_in[1];
    const float* weights  = (const float*)d_in[2];
    float* out = (float*)d_out;

    int n = in_sizes[0] / DIM;   // 2048
    int N = in_sizes[1] / DIM;   // 50000

    int nChunks        = (N + BC - 1) / BC;
    int chunksPerSplit = (nChunks + NSPLIT - 1) / NSPLIT;

    cudaFuncSetAttribute(rbf_fused_kernel,
                         cudaFuncAttributeMaxDynamicSharedMemorySize, SMEM_TOTAL);

    int outN = n * OUTD;
    zero_kernel<<<(outN + 255) / 256, 256>>>(out, outN);

    dim3 grid(n / BM, NSPLIT);
    rbf_fused_kernel<<<grid, THREADS, SMEM_TOTAL>>>(
        features, train, weights, out, N, nChunks, chunksPerSplit);
}

// round 5
// speedup vs baseline: 7.3047x; 7.3047x over previous
#include <cuda_runtime.h>
#include <cuda_bf16.h>
#include <cstdint>

#define DIM 128
#define OUTD 64
#define BC 128
#define SPLITS 9
#define THREADS 256

#define TSTRIDE 136            // bf16 elems per row (A, T tiles)
#define TROWB   (TSTRIDE * 2)  // 272 bytes per row
#define KSTRIDE 132            // fp32 per row of K tile
#define WSTRIDE 64

#define OFF_A   0
#define SZ_A    (128 * TROWB)          // 34816
#define OFF_T   (OFF_A + SZ_A)
#define SZ_T    (128 * TROWB)          // 34816 (x2 buffers)
#define OFF_K   (OFF_T + 2 * SZ_T)     // 104448
#define SZ_K    (128 * KSTRIDE * 4)    // 67584
#define OFF_W   (OFF_K + SZ_K)         // 172032
#define SZ_W    (128 * WSTRIDE * 4)    // 32768
#define OFF_X2  (OFF_W + SZ_W)         // 204800
#define OFF_T2  (OFF_X2 + 512)
#define SMEM_TOTAL (OFF_T2 + 512)      // 205824 bytes

// k = exp(-dist/(2*RBF)) = 2^(-sqrt(d2 * B2C))
#define B2C ((float)((1.4426950408889634 / (2.0 * 10.077141124806595)) * \
                     (1.4426950408889634 / (2.0 * 10.077141124806595))))

// ---------- PTX helpers ----------
__device__ __forceinline__ uint32_t smem_u32(const void* p) {
    uint32_t a;
    asm("{ .reg .u64 t; cvta.to.shared.u64 t, %1; cvt.u32.u64 %0, t; }"
        : "=r"(a) : "l"(p));
    return a;
}
__device__ __forceinline__ void ldsm4(uint32_t* r, uint32_t addr) {
    asm volatile("ldmatrix.sync.aligned.m8n8.x4.shared.b16 {%0,%1,%2,%3}, [%4];"
                 : "=r"(r[0]), "=r"(r[1]), "=r"(r[2]), "=r"(r[3]) : "r"(addr));
}
__device__ __forceinline__ void mma_bf16(float* c, const uint32_t* a, const uint32_t* b) {
    asm volatile("mma.sync.aligned.m16n8k16.row.col.f32.bf16.bf16.f32 "
                 "{%0,%1,%2,%3}, {%4,%5,%6,%7}, {%8,%9}, {%0,%1,%2,%3};"
                 : "+f"(c[0]), "+f"(c[1]), "+f"(c[2]), "+f"(c[3])
                 : "r"(a[0]), "r"(a[1]), "r"(a[2]), "r"(a[3]), "r"(b[0]), "r"(b[1]));
}
__device__ __forceinline__ void mma_tf32(float* c, const uint32_t* a, const uint32_t* b) {
    asm volatile("mma.sync.aligned.m16n8k8.row.col.f32.tf32.tf32.f32 "
                 "{%0,%1,%2,%3}, {%4,%5,%6,%7}, {%8,%9}, {%0,%1,%2,%3};"
                 : "+f"(c[0]), "+f"(c[1]), "+f"(c[2]), "+f"(c[3])
                 : "r"(a[0]), "r"(a[1]), "r"(a[2]), "r"(a[3]), "r"(b[0]), "r"(b[1]));
}
__device__ __forceinline__ uint32_t to_tf32(float f) {
    uint32_t u; asm("cvt.rna.tf32.f32 %0, %1;" : "=r"(u) : "f"(f)); return u;
}
__device__ __forceinline__ float fast_sqrt(float x) {
    float r; asm("sqrt.approx.f32 %0, %1;" : "=f"(r) : "f"(x)); return r;
}
__device__ __forceinline__ float fast_ex2(float x) {
    float r; asm("ex2.approx.f32 %0, %1;" : "=f"(r) : "f"(x)); return r;
}

__global__ void zero_kernel(float* p, int n) {
    int i = blockIdx.x * blockDim.x + threadIdx.x;
    if (i < n) p[i] = 0.0f;
}

// load [rows<=128 x 128] fp32 -> bf16 tile (row-major, stride TSTRIDE elems)
__device__ __forceinline__ void load_bf16_tile(const float* __restrict__ g,
                                               uint8_t* s, int valid) {
    int t = threadIdx.x;
    #pragma unroll
    for (int i = 0; i < 16; i++) {
        int f = t + i * THREADS;       // 0..4095 float4s
        int r = f >> 5, c4 = f & 31;
        float4 v = make_float4(0.f, 0.f, 0.f, 0.f);
        if (r < valid) v = *(const float4*)(g + (size_t)r * DIM + c4 * 4);
        __nv_bfloat162 p0 = __floats2bfloat162_rn(v.x, v.y);
        __nv_bfloat162 p1 = __floats2bfloat162_rn(v.z, v.w);
        // 4 floats -> 4 bf16 = 8 bytes at element offset c4*4 -> byte c4*8
        *(uint2*)(s + r * TROWB + c4 * 8) =
            make_uint2(*(uint32_t*)&p0, *(uint32_t*)&p1);
    }
}

// load W chunk [128 x 64] fp32 -> tf32(fp32 bits) tile, stride WSTRIDE
__device__ __forceinline__ void load_w_tile(const float* __restrict__ w,
                                            uint8_t* s, int c0, int N) {
    int t = threadIdx.x;
    #pragma unroll
    for (int i = 0; i < 8; i++) {
        int f = t + i * THREADS;       // 0..2047 float4s
        int r = f >> 4, c4 = f & 15;
        int gr = c0 + r;
        float4 v = make_float4(0.f, 0.f, 0.f, 0.f);
        if (gr < N) v = *(const float4*)(w + (size_t)gr * OUTD + c4 * 4);
        uint4 u = make_uint4(to_tf32(v.x), to_tf32(v.y), to_tf32(v.z), to_tf32(v.w));
        *(uint4*)(s + (r * WSTRIDE + c4 * 4) * 4) = u;
    }
}

// row norms over a bf16 tile (threads < 128)
__device__ __forceinline__ void bf16_row_norms(const uint8_t* s, float* o) {
    int t = threadIdx.x;
    if (t < 128) {
        float acc = 0.f;
        const uint32_t* row = (const uint32_t*)(s + t * TROWB);
        #pragma unroll
        for (int j = 0; j < 64; j++) {
            float2 f = __bfloat1622float2(*(const __nv_bfloat162*)&row[j]);
            acc = fmaf(f.x, f.x, acc);
            acc = fmaf(f.y, f.y, acc);
        }
        o[t] = acc;
    }
}

__global__ void __launch_bounds__(THREADS, 1)
rbf_mma_kernel(const float* __restrict__ features,
               const float* __restrict__ train,
               const float* __restrict__ weights,
               float* __restrict__ out,
               int N, int nChunks, int cps)
{
    extern __shared__ uint8_t sm[];
    uint32_t smb = smem_u32(sm);

    const int t = threadIdx.x, wid = t >> 5, lid = t & 31;
    const int qr = lid >> 2, qc = lid & 3;
    const int band = wid >> 2;        // 0/1: row band of 64
    const int slice = wid & 3;        // GEMM1: n-cols slice*32
    const int outq = wid & 3;         // GEMM2: out-cols outq*16

    const int rowBase = blockIdx.x * 128;
    const int chunk0  = blockIdx.y * cps;
    const int chunk1  = min(chunk0 + cps, nChunks);
    const int nc      = chunk1 - chunk0;

    float* sX2 = (float*)(sm + OFF_X2);
    float* sT2 = (float*)(sm + OFF_T2);
    float* sK  = (float*)(sm + OFF_K);
    float* sW  = (float*)(sm + OFF_W);

    // ---- prologue: A tile + first T chunk + x2 ----
    load_bf16_tile(features + (size_t)rowBase * DIM, sm + OFF_A, 128);
    load_bf16_tile(train + (size_t)chunk0 * BC * DIM, sm + OFF_T, N - chunk0 * BC);
    __syncthreads();
    bf16_row_norms(sm + OFF_A, sX2);
    __syncthreads();

    // GEMM2 output accumulators: rows band*64 (4 m-tiles), cols outq*16 (2 n-tiles)
    float c2[4][2][4];
    #pragma unroll
    for (int mi = 0; mi < 4; mi++)
        #pragma unroll
        for (int nj = 0; nj < 2; nj++)
            #pragma unroll
            for (int q = 0; q < 4; q++) c2[mi][nj][q] = 0.f;

    for (int i = 0; i < nc; i++) {
        const int ch  = chunk0 + i;
        const int cur = i & 1, nxt = cur ^ 1;

        // ---- GEMM2 for previous chunk (reads sK, sW) ----
        if (i > 0) {
            #pragma unroll
            for (int ks = 0; ks < 16; ks++) {
                const int k0 = ks * 8;
                uint32_t bw[2][2];
                #pragma unroll
                for (int nj = 0; nj < 2; nj++) {
                    int n = outq * 16 + nj * 8 + qr;
                    bw[nj][0] = ((const uint32_t*)sW)[(k0 + qc) * WSTRIDE + n];
                    bw[nj][1] = ((const uint32_t*)sW)[(k0 + qc + 4) * WSTRIDE + n];
                }
                #pragma unroll
                for (int mi = 0; mi < 4; mi++) {
                    int r = band * 64 + mi * 16 + qr;
                    uint32_t a[4];
                    a[0] = ((const uint32_t*)sK)[r * KSTRIDE + k0 + qc];
                    a[1] = ((const uint32_t*)sK)[(r + 8) * KSTRIDE + k0 + qc];
                    a[2] = ((const uint32_t*)sK)[r * KSTRIDE + k0 + qc + 4];
                    a[3] = ((const uint32_t*)sK)[(r + 8) * KSTRIDE + k0 + qc + 4];
                    mma_tf32(c2[mi][0], a, bw[0]);
                    mma_tf32(c2[mi][1], a, bw[1]);
                }
            }
        }
        __syncthreads();   // (A) sW/sK now safe to overwrite

        // ---- loads: next T chunk, this chunk's W ----
        if (i + 1 < nc) {
            int c0n = (ch + 1) * BC;
            load_bf16_tile(train + (size_t)c0n * DIM,
                           sm + OFF_T + nxt * SZ_T, N - c0n);
        }
        load_w_tile(weights, sm + OFF_W, ch * BC, N);

        // ---- GEMM1: S = A(bf16) @ T(bf16)^T,  warp tile 64x32 ----
        float c1[4][4][4];
        #pragma unroll
        for (int mi = 0; mi < 4; mi++)
            #pragma unroll
            for (int nj = 0; nj < 4; nj++)
                #pragma unroll
                for (int q = 0; q < 4; q++) c1[mi][nj][q] = 0.f;

        {
            const uint32_t sAb = smb + OFF_A;
            const uint32_t sTb = smb + OFF_T + cur * SZ_T;
            const int aRow = band * 64 + (lid & 15);
            const int aColHalf = (lid >> 4) << 3;          // 0 or 8
            const int bRowOff = ((lid >> 4) << 3) + (lid & 7);
            const int bColOff = lid & 8;

            #pragma unroll
            for (int ks = 0; ks < 8; ks++) {
                const int k0 = ks * 16;
                uint32_t b[4][2];
                #pragma unroll
                for (int pair = 0; pair < 2; pair++) {
                    uint32_t addr = sTb
                        + (uint32_t)(slice * 32 + pair * 16 + bRowOff) * TROWB
                        + (uint32_t)(k0 + bColOff) * 2;
                    uint32_t rr[4];
                    ldsm4(rr, addr);
                    b[pair * 2][0] = rr[0]; b[pair * 2][1] = rr[1];
                    b[pair * 2 + 1][0] = rr[2]; b[pair * 2 + 1][1] = rr[3];
                }
                #pragma unroll
                for (int mi = 0; mi < 4; mi++) {
                    uint32_t addr = sAb
                        + (uint32_t)(aRow + mi * 16) * TROWB
                        + (uint32_t)(k0 + aColHalf) * 2;
                    uint32_t a[4];
                    ldsm4(a, addr);
                    #pragma unroll
                    for (int nj = 0; nj < 4; nj++)
                        mma_bf16(c1[mi][nj], a, b[nj]);
                }
            }
        }

        // ---- t2 of current chunk ----
        bf16_row_norms(sm + OFF_T + cur * SZ_T, sT2);
        __syncthreads();   // (B) t2 ready, T[nxt]/W stored

        // ---- epilogue: d2 -> k, store K (tf32 bits) to SMEM ----
        #pragma unroll
        for (int mi = 0; mi < 4; mi++) {
            int r = band * 64 + mi * 16 + qr;
            float x2lo = sX2[r], x2hi = sX2[r + 8];
            #pragma unroll
            for (int nj = 0; nj < 4; nj++) {
                int cl = slice * 32 + nj * 8 + 2 * qc;
                float2 t2p = *(float2*)&sT2[cl];
                float d00 = fmaxf(fmaf(-2.f, c1[mi][nj][0], x2lo + t2p.x), 0.f);
                float d01 = fmaxf(fmaf(-2.f, c1[mi][nj][1], x2lo + t2p.y), 0.f);
                float d10 = fmaxf(fmaf(-2.f, c1[mi][nj][2], x2hi + t2p.x), 0.f);
                float d11 = fmaxf(fmaf(-2.f, c1[mi][nj][3], x2hi + t2p.y), 0.f);
                float k00 = fast_ex2(-fast_sqrt(d00 * B2C));
                float k01 = fast_ex2(-fast_sqrt(d01 * B2C));
                float k10 = fast_ex2(-fast_sqrt(d10 * B2C));
                float k11 = fast_ex2(-fast_sqrt(d11 * B2C));
                *(uint2*)&sK[r * KSTRIDE + cl] =
                    make_uint2(to_tf32(k00), to_tf32(k01));
                *(uint2*)&sK[(r + 8) * KSTRIDE + cl] =
                    make_uint2(to_tf32(k10), to_tf32(k11));
            }
        }
        __syncthreads();   // (C) sK ready for next-iteration GEMM2
    }

    // ---- final GEMM2 for last chunk ----
    #pragma unroll
    for (int ks = 0; ks < 16; ks++) {
        const int k0 = ks * 8;
        uint32_t bw[2][2];
        #pragma unroll
        for (int nj = 0; nj < 2; nj++) {
            int n = outq * 16 + nj * 8 + qr;
            bw[nj][0] = ((const uint32_t*)sW)[(k0 + qc) * WSTRIDE + n];
            bw[nj][1] = ((const uint32_t*)sW)[(k0 + qc + 4) * WSTRIDE + n];
        }
        #pragma unroll
        for (int mi = 0; mi < 4; mi++) {
            int r = band * 64 + mi * 16 + qr;
            uint32_t a[4];
            a[0] = ((const uint32_t*)sK)[r * KSTRIDE + k0 + qc];
            a[1] = ((const uint32_t*)sK)[(r + 8) * KSTRIDE + k0 + qc];
            a[2] = ((const uint32_t*)sK)[r * KSTRIDE + k0 + qc + 4];
            a[3] = ((const uint32_t*)sK)[(r + 8) * KSTRIDE + k0 + qc + 4];
            mma_tf32(c2[mi][0], a, bw[0]);
            mma_tf32(c2[mi][1], a, bw[1]);
        }
    }

    // ---- accumulate into global out (split-K across blockIdx.y) ----
    #pragma unroll
    for (int mi = 0; mi < 4; mi++) {
        int r = rowBase + band * 64 + mi * 16 + qr;
        #pragma unroll
        for (int nj = 0; nj < 2; nj++) {
            int c = outq * 16 + nj * 8 + 2 * qc;
            atomicAdd(out + (size_t)r * OUTD + c,            c2[mi][nj][0]);
            atomicAdd(out + (size_t)r * OUTD + c + 1,        c2[mi][nj][1]);
            atomicAdd(out + (size_t)(r + 8) * OUTD + c,      c2[mi][nj][2]);
            atomicAdd(out + (size_t)(r + 8) * OUTD + c + 1,  c2[mi][nj][3]);
        }
    }
}

extern "C" void kernel_launch(void* const* d_in, const int* in_sizes, int n_in,
                              void* d_out, int out_size) {
    const float* features = (const float*)d_in[0];
    const float* train    = (const float*)d_in[1];
    const float* weights  = (const float*)d_in[2];
    float* out = (float*)d_out;

    int n = in_sizes[0] / DIM;    // 2048
    int N = in_sizes[1] / DIM;    // 50000

    int nChunks = (N + BC - 1) / BC;                 // 391
    int cps     = (nChunks + SPLITS - 1) / SPLITS;   // 44

    cudaFuncSetAttribute(rbf_mma_kernel,
                         cudaFuncAttributeMaxDynamicSharedMemorySize, SMEM_TOTAL);

    int outN = n * OUTD;
    zero_kernel<<<(outN + 255) / 256, 256>>>(out, outN);

    dim3 grid(n / 128, SPLITS);
    rbf_mma_kernel<<<grid, THREADS, SMEM_TOTAL>>>(
        features, train, weights, out, N, nChunks, cps);
}

// round 6
// speedup vs baseline: 9.9895x; 1.3675x over previous
#include <cuda_runtime.h>
#include <cuda_bf16.h>
#include <cstdint>

#define DIM 128
#define OUTD 64
#define BC 128
#define SPLITS 9
#define THREADS 256

#define TSTRIDE 136            // bf16 per row of A/T tiles
#define TROWB   (TSTRIDE * 2)  // 272 B
#define WPAD    72             // bf16 per row of W tiles (k-major)
#define WROWB   (WPAD * 2)     // 144 B

#define OFF_A   0
#define SZ_A    (128 * TROWB)              // 34816
#define OFF_T   (OFF_A + SZ_A)
#define SZ_T    (128 * TROWB)              // 34816 x2 buffers
#define OFF_W   (OFF_T + 2 * SZ_T)         // 104448
#define SZ_WP   (128 * WROWB)              // 18432 (one part)
#define SZ_WB   (2 * SZ_WP)                // 36864 (hi+lo)  x2 buffers
#define OFF_X2  (OFF_W + 2 * SZ_WB)        // 178176
#define OFF_T2  (OFF_X2 + 512)
#define SMEM_TOTAL (OFF_T2 + 512)          // 179200

// k = exp(-dist/(2*RBF)) = 2^(-sqrt(d2 * B2C))
#define B2C ((float)((1.4426950408889634 / (2.0 * 10.077141124806595)) * \
                     (1.4426950408889634 / (2.0 * 10.077141124806595))))

// ---------- PTX helpers ----------
__device__ __forceinline__ uint32_t smem_u32(const void* p) {
    uint32_t a;
    asm("{ .reg .u64 t; cvta.to.shared.u64 t, %1; cvt.u32.u64 %0, t; }"
        : "=r"(a) : "l"(p));
    return a;
}
__device__ __forceinline__ void ldsm4(uint32_t* r, uint32_t addr) {
    asm volatile("ldmatrix.sync.aligned.m8n8.x4.shared.b16 {%0,%1,%2,%3}, [%4];"
                 : "=r"(r[0]), "=r"(r[1]), "=r"(r[2]), "=r"(r[3]) : "r"(addr));
}
__device__ __forceinline__ void ldsm4t(uint32_t* r, uint32_t addr) {
    asm volatile("ldmatrix.sync.aligned.m8n8.x4.trans.shared.b16 {%0,%1,%2,%3}, [%4];"
                 : "=r"(r[0]), "=r"(r[1]), "=r"(r[2]), "=r"(r[3]) : "r"(addr));
}
__device__ __forceinline__ void mma_bf16(float* c, const uint32_t* a, const uint32_t* b) {
    asm volatile("mma.sync.aligned.m16n8k16.row.col.f32.bf16.bf16.f32 "
                 "{%0,%1,%2,%3}, {%4,%5,%6,%7}, {%8,%9}, {%0,%1,%2,%3};"
                 : "+f"(c[0]), "+f"(c[1]), "+f"(c[2]), "+f"(c[3])
                 : "r"(a[0]), "r"(a[1]), "r"(a[2]), "r"(a[3]), "r"(b[0]), "r"(b[1]));
}
__device__ __forceinline__ float fast_sqrt(float x) {
    float r; asm("sqrt.approx.f32 %0, %1;" : "=f"(r) : "f"(x)); return r;
}
__device__ __forceinline__ float fast_ex2(float x) {
    float r; asm("ex2.approx.f32 %0, %1;" : "=f"(r) : "f"(x)); return r;
}
__device__ __forceinline__ uint32_t pack_bf16(__nv_bfloat16 a, __nv_bfloat16 b) {
    __nv_bfloat162 p = __halves2bfloat162(a, b);
    return *(uint32_t*)&p;
}

__global__ void zero_kernel(float* p, int n) {
    int i = blockIdx.x * blockDim.x + threadIdx.x;
    if (i < n) p[i] = 0.0f;
}

// [rows<=128 x 128] fp32 -> bf16 tile (row-major, stride TSTRIDE elems)
__device__ __forceinline__ void load_bf16_tile(const float* __restrict__ g,
                                               uint8_t* s, int valid) {
    int t = threadIdx.x;
    #pragma unroll
    for (int i = 0; i < 16; i++) {
        int f = t + i * THREADS;       // 0..4095 float4s
        int r = f >> 5, c4 = f & 31;
        float4 v = make_float4(0.f, 0.f, 0.f, 0.f);
        if (r < valid) v = *(const float4*)(g + (size_t)r * DIM + c4 * 4);
        __nv_bfloat162 p0 = __floats2bfloat162_rn(v.x, v.y);
        __nv_bfloat162 p1 = __floats2bfloat162_rn(v.z, v.w);
        *(uint2*)(s + r * TROWB + c4 * 8) =
            make_uint2(*(uint32_t*)&p0, *(uint32_t*)&p1);
    }
}

// W chunk [128 x 64] fp32 -> bf16 hi/lo k-major tiles (row=k, WPAD stride)
__device__ __forceinline__ void load_w_split(const float* __restrict__ w,
                                             uint8_t* sHi, uint8_t* sLo,
                                             int c0, int N) {
    int t = threadIdx.x;
    #pragma unroll
    for (int i = 0; i < 8; i++) {
        int f = t + i * THREADS;       // 0..2047 float4s
        int r = f >> 4, c4 = f & 15;
        int gr = c0 + r;
        float4 v = make_float4(0.f, 0.f, 0.f, 0.f);
        if (gr < N) v = *(const float4*)(w + (size_t)gr * OUTD + c4 * 4);
        __nv_bfloat16 hx = __float2bfloat16_rn(v.x);
        __nv_bfloat16 hy = __float2bfloat16_rn(v.y);
        __nv_bfloat16 hz = __float2bfloat16_rn(v.z);
        __nv_bfloat16 hw = __float2bfloat16_rn(v.w);
        float lx = v.x - __bfloat162float(hx);
        float ly = v.y - __bfloat162float(hy);
        float lz = v.z - __bfloat162float(hz);
        float lw = v.w - __bfloat162float(hw);
        *(uint2*)(sHi + r * WROWB + c4 * 8) =
            make_uint2(pack_bf16(hx, hy), pack_bf16(hz, hw));
        *(uint2*)(sLo + r * WROWB + c4 * 8) =
            make_uint2(pack_bf16(__float2bfloat16_rn(lx), __float2bfloat16_rn(ly)),
                       pack_bf16(__float2bfloat16_rn(lz), __float2bfloat16_rn(lw)));
    }
}

// row norms over a bf16 tile (threads < 128)
__device__ __forceinline__ void bf16_row_norms(const uint8_t* s, float* o) {
    int t = threadIdx.x;
    if (t < 128) {
        float acc = 0.f;
        const uint32_t* row = (const uint32_t*)(s + t * TROWB);
        #pragma unroll
        for (int j = 0; j < 64; j++) {
            float2 f = __bfloat1622float2(*(const __nv_bfloat162*)&row[j]);
            acc = fmaf(f.x, f.x, acc);
            acc = fmaf(f.y, f.y, acc);
        }
        o[t] = acc;
    }
}

__global__ void __launch_bounds__(THREADS, 1)
rbf_regfused_kernel(const float* __restrict__ features,
                    const float* __restrict__ train,
                    const float* __restrict__ weights,
                    float* __restrict__ out,
                    int N, int nChunks, int cps)
{
    extern __shared__ uint8_t sm[];
    uint32_t smb = smem_u32(sm);

    const int t = threadIdx.x, wid = t >> 5, lid = t & 31;
    const int qr = lid >> 2, qc = lid & 3;
    const int kh = wid & 1;          // k-half of the chunk (cols kh*64..)
    const int mb = wid >> 1;         // row band of 32: rows mb*32..

    const int rowBase = blockIdx.x * 128;
    const int chunk0  = blockIdx.y * cps;
    const int chunk1  = min(chunk0 + cps, nChunks);
    const int nc      = chunk1 - chunk0;

    float* sX2 = (float*)(sm + OFF_X2);
    float* sT2 = (float*)(sm + OFF_T2);

    // ---- prologue ----
    load_bf16_tile(features + (size_t)rowBase * DIM, sm + OFF_A, 128);
    load_bf16_tile(train + (size_t)chunk0 * BC * DIM, sm + OFF_T, N - chunk0 * BC);
    load_w_split(weights, sm + OFF_W, sm + OFF_W + SZ_WP, chunk0 * BC, N);
    __syncthreads();
    bf16_row_norms(sm + OFF_A, sX2);

    // fragment address helpers
    const int aRowL    = lid & 15;
    const int aColHalf = (lid >> 4) << 3;
    const int bRowOff  = ((lid >> 4) << 3) + (lid & 7);
    const int bColOff  = lid & 8;
    // W trans-ldsm lane addressing
    const int wKrow = (((lid >> 3) & 1) << 3) + (lid & 7);
    const int wNcol = (lid >> 4) << 3;

    float c2[2][8][4];
    #pragma unroll
    for (int mi = 0; mi < 2; mi++)
        #pragma unroll
        for (int nt = 0; nt < 8; nt++)
            #pragma unroll
            for (int q = 0; q < 4; q++) c2[mi][nt][q] = 0.f;

    for (int i = 0; i < nc; i++) {
        const int cur = i & 1, nxt = cur ^ 1;
        const uint32_t sTb = smb + OFF_T + cur * SZ_T;
        const uint32_t sWb = smb + OFF_W + cur * SZ_WB;

        __syncthreads();   // loads into [cur] complete; [nxt] free to rewrite

        // t2 of current chunk
        bf16_row_norms(sm + OFF_T + cur * SZ_T, sT2);

        // prefetch next chunk into [nxt]
        if (i + 1 < nc) {
            int c0n = (chunk0 + i + 1) * BC;
            load_bf16_tile(train + (size_t)c0n * DIM, sm + OFF_T + nxt * SZ_T,
                           N - c0n);
            load_w_split(weights, sm + OFF_W + nxt * SZ_WB,
                         sm + OFF_W + nxt * SZ_WB + SZ_WP, c0n, N);
        }
        __syncthreads();   // t2 visible

        // ---- GEMM1: c1 = A[mb*32.., :] @ T[kh*64.., :]^T  (32x64) ----
        float c1[2][8][4];
        #pragma unroll
        for (int mi = 0; mi < 2; mi++)
            #pragma unroll
            for (int nj = 0; nj < 8; nj++)
                #pragma unroll
                for (int q = 0; q < 4; q++) c1[mi][nj][q] = 0.f;

        #pragma unroll
        for (int ks = 0; ks < 8; ks++) {
            const int k0 = ks * 16;
            uint32_t a[2][4];
            #pragma unroll
            for (int mi = 0; mi < 2; mi++)
                ldsm4(a[mi], smb + OFF_A
                      + (uint32_t)(mb * 32 + mi * 16 + aRowL) * TROWB
                      + (uint32_t)(k0 + aColHalf) * 2);
            uint32_t b[8][2];
            #pragma unroll
            for (int p = 0; p < 4; p++) {
                uint32_t rr[4];
                ldsm4(rr, sTb
                      + (uint32_t)(kh * 64 + p * 16 + bRowOff) * TROWB
                      + (uint32_t)(k0 + bColOff) * 2);
                b[2 * p][0] = rr[0]; b[2 * p][1] = rr[1];
                b[2 * p + 1][0] = rr[2]; b[2 * p + 1][1] = rr[3];
            }
            #pragma unroll
            for (int mi = 0; mi < 2; mi++)
                #pragma unroll
                for (int nj = 0; nj < 8; nj++)
                    mma_bf16(c1[mi][nj], a[mi], b[nj]);
        }

        // ---- epilogue in registers: d2 -> k, pack bf16 hi/lo A-frags ----
        uint32_t ahi[2][4][4], alo[2][4][4];
        {
            float x2v[2][2];
            #pragma unroll
            for (int mi = 0; mi < 2; mi++) {
                x2v[mi][0] = sX2[mb * 32 + mi * 16 + qr];
                x2v[mi][1] = sX2[mb * 32 + mi * 16 + qr + 8];
            }
            #pragma unroll
            for (int s = 0; s < 4; s++) {
                const int cb = kh * 64 + s * 16;
                float2 t2a = *(float2*)&sT2[cb + 2 * qc];      // nj=2s
                float2 t2b = *(float2*)&sT2[cb + 8 + 2 * qc];  // nj=2s+1
                #pragma unroll
                for (int mi = 0; mi < 2; mi++) {
                    float kk[2][4];  // [njpair][q]
                    #pragma unroll
                    for (int half = 0; half < 2; half++) {
                        const float* cc = c1[mi][2 * s + half];
                        float2 t2p = half ? t2b : t2a;
                        #pragma unroll
                        for (int q = 0; q < 4; q++) {
                            float x2q = x2v[mi][q >> 1];
                            float tq  = (q & 1) ? t2p.y : t2p.x;
                            float d2  = fmaxf(fmaf(-2.f, cc[q], x2q + tq), 0.f);
                            kk[half][q] = fast_ex2(-fast_sqrt(d2 * B2C));
                        }
                    }
                    // A-frag: a[0]={k(2s,q0),k(2s,q1)} a[1]={k(2s,q2),k(2s,q3)}
                    //         a[2]={k(2s+1,q0),...}    a[3]={k(2s+1,q2),...}
                    #pragma unroll
                    for (int r = 0; r < 4; r++) {
                        float va = kk[r >> 1][(r & 1) * 2];
                        float vb = kk[r >> 1][(r & 1) * 2 + 1];
                        __nv_bfloat16 ha = __float2bfloat16_rn(va);
                        __nv_bfloat16 hb = __float2bfloat16_rn(vb);
                        ahi[mi][s][r] = pack_bf16(ha, hb);
                        alo[mi][s][r] = pack_bf16(
                            __float2bfloat16_rn(va - __bfloat162float(ha)),
                            __float2bfloat16_rn(vb - __bfloat162float(hb)));
                    }
                }
            }
        }

        // ---- GEMM2: c2 += K(32 x 64slice) @ W[kh*64.., :]  (3-term split) ----
        #pragma unroll
        for (int s = 0; s < 4; s++) {
            const uint32_t wrow = (uint32_t)(kh * 64 + s * 16 + wKrow) * WROWB;
            #pragma unroll
            for (int u = 0; u < 4; u++) {
                uint32_t addr = sWb + wrow + (uint32_t)(u * 16 + wNcol) * 2;
                uint32_t bh[4], bl[4];
                ldsm4t(bh, addr);
                ldsm4t(bl, addr + SZ_WP);
                #pragma unroll
                for (int mi = 0; mi < 2; mi++)
                    #pragma unroll
                    for (int v = 0; v < 2; v++) {
                        float* cc = c2[mi][2 * u + v];
                        mma_bf16(cc, ahi[mi][s], &bh[2 * v]);
                        mma_bf16(cc, ahi[mi][s], &bl[2 * v]);
                        mma_bf16(cc, alo[mi][s], &bh[2 * v]);
                    }
            }
        }
    }

    // ---- accumulate into global out (split over blockIdx.y and k-halves) ----
    #pragma unroll
    for (int mi = 0; mi < 2; mi++) {
        #pragma unroll
        for (int nt = 0; nt < 8; nt++) {
            int c = nt * 8 + 2 * qc;
            #pragma unroll
            for (int q = 0; q < 4; q++) {
                int r = rowBase + mb * 32 + mi * 16 + qr + ((q >> 1) << 3);
                atomicAdd(out + (size_t)r * OUTD + c + (q & 1), c2[mi][nt][q]);
            }
        }
    }
}

extern "C" void kernel_launch(void* const* d_in, const int* in_sizes, int n_in,
                              void* d_out, int out_size) {
    const float* features = (const float*)d_in[0];
    const float* train    = (const float*)d_in[1];
    const float* weights  = (const float*)d_in[2];
    float* out = (float*)d_out;

    int n = in_sizes[0] / DIM;    // 2048
    int N = in_sizes[1] / DIM;    // 50000

    int nChunks = (N + BC - 1) / BC;                 // 391
    int cps     = (nChunks + SPLITS - 1) / SPLITS;   // 44

    cudaFuncSetAttribute(rbf_regfused_kernel,
                         cudaFuncAttributeMaxDynamicSharedMemorySize, SMEM_TOTAL);

    int outN = n * OUTD;
    zero_kernel<<<(outN + 255) / 256, 256>>>(out, outN);

    dim3 grid(n / 128, SPLITS);
    rbf_regfused_kernel<<<grid, THREADS, SMEM_TOTAL>>>(
        features, train, weights, out, N, nChunks, cps);
}

// round 7
// speedup vs baseline: 14.4227x; 1.4438x over previous
#include <cuda_runtime.h>
#include <cuda_fp16.h>
#include <cstdint>

#define DIM 128
#define OUTD 64
#define BC 128
#define SPLITS 9
#define THREADS 256

#define TSTRIDE 136            // fp16 per row of A/T tiles
#define TROWB   (TSTRIDE * 2)  // 272 B
#define WPAD    72             // fp16 per row of W tile (k-major)
#define WROWB   (WPAD * 2)     // 144 B

#define OFF_A   0
#define SZ_A    (128 * TROWB)              // 34816
#define OFF_T   (OFF_A + SZ_A)
#define SZ_T    (128 * TROWB)              // 34816 x2 buffers
#define OFF_W   (OFF_T + 2 * SZ_T)         // 104448
#define SZ_W    (128 * WROWB)              // 18432  x2 buffers
#define OFF_X2  (OFF_W + 2 * SZ_W)         // 141312
#define OFF_T2  (OFF_X2 + 512)
#define SMEM_TOTAL (OFF_T2 + 512)          // 142336

// k = exp(-dist/(2*RBF)) = 2^(-sqrt(d2 * B2C));  norms pre-scaled by B2C
#define B2C ((float)((1.4426950408889634 / (2.0 * 10.077141124806595)) * \
                     (1.4426950408889634 / (2.0 * 10.077141124806595))))
#define NEG2B2C (-2.0f * B2C)

// ---------- PTX helpers ----------
__device__ __forceinline__ uint32_t smem_u32(const void* p) {
    uint32_t a;
    asm("{ .reg .u64 t; cvta.to.shared.u64 t, %1; cvt.u32.u64 %0, t; }"
        : "=r"(a) : "l"(p));
    return a;
}
__device__ __forceinline__ void ldsm4(uint32_t* r, uint32_t addr) {
    asm volatile("ldmatrix.sync.aligned.m8n8.x4.shared.b16 {%0,%1,%2,%3}, [%4];"
                 : "=r"(r[0]), "=r"(r[1]), "=r"(r[2]), "=r"(r[3]) : "r"(addr));
}
__device__ __forceinline__ void ldsm4t(uint32_t* r, uint32_t addr) {
    asm volatile("ldmatrix.sync.aligned.m8n8.x4.trans.shared.b16 {%0,%1,%2,%3}, [%4];"
                 : "=r"(r[0]), "=r"(r[1]), "=r"(r[2]), "=r"(r[3]) : "r"(addr));
}
__device__ __forceinline__ void mma_f16(float* c, const uint32_t* a, const uint32_t* b) {
    asm volatile("mma.sync.aligned.m16n8k16.row.col.f32.f16.f16.f32 "
                 "{%0,%1,%2,%3}, {%4,%5,%6,%7}, {%8,%9}, {%0,%1,%2,%3};"
                 : "+f"(c[0]), "+f"(c[1]), "+f"(c[2]), "+f"(c[3])
                 : "r"(a[0]), "r"(a[1]), "r"(a[2]), "r"(a[3]), "r"(b[0]), "r"(b[1]));
}
__device__ __forceinline__ float fast_sqrt(float x) {
    float r; asm("sqrt.approx.f32 %0, %1;" : "=f"(r) : "f"(x)); return r;
}
__device__ __forceinline__ float fast_ex2(float x) {
    float r; asm("ex2.approx.f32 %0, %1;" : "=f"(r) : "f"(x)); return r;
}
__device__ __forceinline__ uint32_t pack_h2(float a, float b) {
    __half2 p = __floats2half2_rn(a, b);
    return *(uint32_t*)&p;
}

__global__ void zero_kernel(float* p, int n) {
    int i = blockIdx.x * blockDim.x + threadIdx.x;
    if (i < n) p[i] = 0.0f;
}

// [rows<=128 x 128] fp32 -> fp16 tile (row-major, stride TSTRIDE elems)
__device__ __forceinline__ void load_f16_tile(const float* __restrict__ g,
                                              uint8_t* s, int valid) {
    int t = threadIdx.x;
    #pragma unroll
    for (int i = 0; i < 16; i++) {
        int f = t + i * THREADS;       // 0..4095 float4s
        int r = f >> 5, c4 = f & 31;
        float4 v = make_float4(0.f, 0.f, 0.f, 0.f);
        if (r < valid) v = *(const float4*)(g + (size_t)r * DIM + c4 * 4);
        *(uint2*)(s + r * TROWB + c4 * 8) =
            make_uint2(pack_h2(v.x, v.y), pack_h2(v.z, v.w));
    }
}

// W chunk [128 x 64] fp32 -> fp16 k-major tile (row=k, WPAD stride)
__device__ __forceinline__ void load_w_f16(const float* __restrict__ w,
                                           uint8_t* s, int c0, int N) {
    int t = threadIdx.x;
    #pragma unroll
    for (int i = 0; i < 8; i++) {
        int f = t + i * THREADS;       // 0..2047 float4s
        int r = f >> 4, c4 = f & 15;
        int gr = c0 + r;
        float4 v = make_float4(0.f, 0.f, 0.f, 0.f);
        if (gr < N) v = *(const float4*)(w + (size_t)gr * OUTD + c4 * 4);
        *(uint2*)(s + r * WROWB + c4 * 8) =
            make_uint2(pack_h2(v.x, v.y), pack_h2(v.z, v.w));
    }
}

// row norms over an fp16 tile (threads < 128), pre-scaled by B2C
__device__ __forceinline__ void f16_row_norms(const uint8_t* s, float* o) {
    int t = threadIdx.x;
    if (t < 128) {
        float acc = 0.f;
        const uint32_t* row = (const uint32_t*)(s + t * TROWB);
        #pragma unroll
        for (int j = 0; j < 64; j++) {
            float2 f = __half22float2(*(const __half2*)&row[j]);
            acc = fmaf(f.x, f.x, acc);
            acc = fmaf(f.y, f.y, acc);
        }
        o[t] = acc * B2C;
    }
}

__global__ void __launch_bounds__(THREADS, 1)
rbf_f16_kernel(const float* __restrict__ features,
               const float* __restrict__ train,
               const float* __restrict__ weights,
               float* __restrict__ out,
               int N, int nChunks, int cps)
{
    extern __shared__ uint8_t sm[];
    uint32_t smb = smem_u32(sm);

    const int t = threadIdx.x, wid = t >> 5, lid = t & 31;
    const int qr = lid >> 2, qc = lid & 3;
    const int kh = wid & 1;          // k-half of the chunk (cols kh*64..)
    const int mb = wid >> 1;         // row band of 32: rows mb*32..

    const int rowBase = blockIdx.x * 128;
    const int chunk0  = blockIdx.y * cps;
    const int chunk1  = min(chunk0 + cps, nChunks);
    const int nc      = chunk1 - chunk0;

    float* sX2 = (float*)(sm + OFF_X2);
    float* sT2 = (float*)(sm + OFF_T2);

    // ---- prologue ----
    load_f16_tile(features + (size_t)rowBase * DIM, sm + OFF_A, 128);
    load_f16_tile(train + (size_t)chunk0 * BC * DIM, sm + OFF_T, N - chunk0 * BC);
    load_w_f16(weights, sm + OFF_W, chunk0 * BC, N);
    __syncthreads();
    f16_row_norms(sm + OFF_A, sX2);

    // fragment address helpers
    const int aRowL    = lid & 15;
    const int aColHalf = (lid >> 4) << 3;
    const int bRowOff  = ((lid >> 4) << 3) + (lid & 7);
    const int bColOff  = lid & 8;
    const int wKrow = (((lid >> 3) & 1) << 3) + (lid & 7);
    const int wNcol = (lid >> 4) << 3;

    float c2[2][8][4];
    #pragma unroll
    for (int mi = 0; mi < 2; mi++)
        #pragma unroll
        for (int nt = 0; nt < 8; nt++)
            #pragma unroll
            for (int q = 0; q < 4; q++) c2[mi][nt][q] = 0.f;

    for (int i = 0; i < nc; i++) {
        const int cur = i & 1, nxt = cur ^ 1;
        const uint32_t sTb = smb + OFF_T + cur * SZ_T;
        const uint32_t sWb = smb + OFF_W + cur * SZ_W;

        __syncthreads();   // loads into [cur] complete; [nxt] free to rewrite

        // t2 of current chunk (pre-scaled by B2C)
        f16_row_norms(sm + OFF_T + cur * SZ_T, sT2);

        // prefetch next chunk into [nxt]
        if (i + 1 < nc) {
            int c0n = (chunk0 + i + 1) * BC;
            load_f16_tile(train + (size_t)c0n * DIM, sm + OFF_T + nxt * SZ_T,
                          N - c0n);
            load_w_f16(weights, sm + OFF_W + nxt * SZ_W, c0n, N);
        }
        __syncthreads();   // t2 visible

        // ---- GEMM1: c1 = A[mb*32.., :] @ T[kh*64.., :]^T  (32x64) ----
        float c1[2][8][4];
        #pragma unroll
        for (int mi = 0; mi < 2; mi++)
            #pragma unroll
            for (int nj = 0; nj < 8; nj++)
                #pragma unroll
                for (int q = 0; q < 4; q++) c1[mi][nj][q] = 0.f;

        #pragma unroll
        for (int ks = 0; ks < 8; ks++) {
            const int k0 = ks * 16;
            uint32_t a[2][4];
            #pragma unroll
            for (int mi = 0; mi < 2; mi++)
                ldsm4(a[mi], smb + OFF_A
                      + (uint32_t)(mb * 32 + mi * 16 + aRowL) * TROWB
                      + (uint32_t)(k0 + aColHalf) * 2);
            uint32_t b[8][2];
            #pragma unroll
            for (int p = 0; p < 4; p++) {
                uint32_t rr[4];
                ldsm4(rr, sTb
                      + (uint32_t)(kh * 64 + p * 16 + bRowOff) * TROWB
                      + (uint32_t)(k0 + bColOff) * 2);
                b[2 * p][0] = rr[0]; b[2 * p][1] = rr[1];
                b[2 * p + 1][0] = rr[2]; b[2 * p + 1][1] = rr[3];
            }
            #pragma unroll
            for (int mi = 0; mi < 2; mi++)
                #pragma unroll
                for (int nj = 0; nj < 8; nj++)
                    mma_f16(c1[mi][nj], a[mi], b[nj]);
        }

        // x2 (pre-scaled) for this warp's rows
        float x2v[2][2];
        #pragma unroll
        for (int mi = 0; mi < 2; mi++) {
            x2v[mi][0] = sX2[mb * 32 + mi * 16 + qr];
            x2v[mi][1] = sX2[mb * 32 + mi * 16 + qr + 8];
        }

        // ---- per-16-col slice: epilogue -> A-frag -> GEMM2 ----
        #pragma unroll
        for (int s = 0; s < 4; s++) {
            const int cb = kh * 64 + s * 16;
            float2 t2a = *(float2*)&sT2[cb + 2 * qc];      // nj=2s
            float2 t2b = *(float2*)&sT2[cb + 8 + 2 * qc];  // nj=2s+1
            uint32_t ah[2][4];
            #pragma unroll
            for (int mi = 0; mi < 2; mi++) {
                float kk[2][4];
                #pragma unroll
                for (int half = 0; half < 2; half++) {
                    const float* cc = c1[mi][2 * s + half];
                    float2 t2p = half ? t2b : t2a;
                    #pragma unroll
                    for (int q = 0; q < 4; q++) {
                        float x2q = x2v[mi][q >> 1];
                        float tq  = (q & 1) ? t2p.y : t2p.x;
                        float d2  = fmaxf(fmaf(NEG2B2C, cc[q], x2q + tq), 0.f);
                        kk[half][q] = fast_ex2(-fast_sqrt(d2));
                    }
                }
                #pragma unroll
                for (int r = 0; r < 4; r++)
                    ah[mi][r] = pack_h2(kk[r >> 1][(r & 1) * 2],
                                        kk[r >> 1][(r & 1) * 2 + 1]);
            }

            const uint32_t wrow = (uint32_t)(kh * 64 + s * 16 + wKrow) * WROWB;
            #pragma unroll
            for (int u = 0; u < 4; u++) {
                uint32_t bh[4];
                ldsm4t(bh, sWb + wrow + (uint32_t)(u * 16 + wNcol) * 2);
                #pragma unroll
                for (int mi = 0; mi < 2; mi++)
                    #pragma unroll
                    for (int v = 0; v < 2; v++)
                        mma_f16(c2[mi][2 * u + v], ah[mi], &bh[2 * v]);
            }
        }
    }

    // ---- accumulate into global out (split over blockIdx.y and k-halves) ----
    #pragma unroll
    for (int mi = 0; mi < 2; mi++) {
        #pragma unroll
        for (int nt = 0; nt < 8; nt++) {
            int c = nt * 8 + 2 * qc;
            #pragma unroll
            for (int q = 0; q < 4; q++) {
                int r = rowBase + mb * 32 + mi * 16 + qr + ((q >> 1) << 3);
                atomicAdd(out + (size_t)r * OUTD + c + (q & 1), c2[mi][nt][q]);
            }
        }
    }
}

extern "C" void kernel_launch(void* const* d_in, const int* in_sizes, int n_in,
                              void* d_out, int out_size) {
    const float* features = (const float*)d_in[0];
    const float* train    = (const float*)d_in[1];
    const float* weights  = (const float*)d_in[2];
    float* out = (float*)d_out;

    int n = in_sizes[0] / DIM;    // 2048
    int N = in_sizes[1] / DIM;    // 50000

    int nChunks = (N + BC - 1) / BC;                 // 391
    int cps     = (nChunks + SPLITS - 1) / SPLITS;   // 44

    cudaFuncSetAttribute(rbf_f16_kernel,
                         cudaFuncAttributeMaxDynamicSharedMemorySize, SMEM_TOTAL);

    int outN = n * OUTD;
    zero_kernel<<<(outN + 255) / 256, 256>>>(out, outN);

    dim3 grid(n / 128, SPLITS);
    rbf_f16_kernel<<<grid, THREADS, SMEM_TOTAL>>>(
        features, train, weights, out, N, nChunks, cps);
}

// round 8
// speedup vs baseline: 14.4933x; 1.0049x over previous
#include <cuda_runtime.h>
#include <cuda_fp16.h>
#include <cstdint>

#define DIM 128
#define OUTD 64
#define BC 128
#define SPLITS 9
#define THREADS 256
#define NPAD 50048              // 391 * 128, padded train rows
#define NFEAT 2048

#define TSTRIDE 136             // fp16 per row of A/T tiles
#define TROWB   (TSTRIDE * 2)   // 272 B (= 17*16, cp.async 16B-aligned)
#define WROWB   144             // W tile row bytes (= 9*16)

#define OFF_A   0
#define SZ_A    (128 * TROWB)             // 34816
#define OFF_T   (OFF_A + SZ_A)
#define SZ_T    (128 * TROWB)             // 34816 x2
#define OFF_W   (OFF_T + 2 * SZ_T)        // 104448
#define SZ_W    (128 * WROWB)             // 18432 x2
#define OFF_T2  (OFF_W + 2 * SZ_W)        // 141312, 2 x 512B
#define SMEM_TOTAL (OFF_T2 + 1024)        // 142336

// k = exp(-dist/(2*RBF)) = 2^(-sqrt(d2p)), d2p = B2C*(x2 + t2 - 2 dot)
#define B2C ((float)((1.4426950408889634 / (2.0 * 10.077141124806595)) * \
                     (1.4426950408889634 / (2.0 * 10.077141124806595))))
#define NEG2B2C (-2.0f * B2C)

// ---- persistent device scratch (allowed: __device__ globals) ----
__device__ __half d_train16[NPAD * DIM];    // fp16 train, pad rows = 0
__device__ __half d_w16[NPAD * OUTD];       // fp16 weights, pad rows = 0
__device__ __half d_feat16[NFEAT * DIM];    // fp16 features
__device__ float  d_t2[NPAD];               // B2C * ||t~||^2 (fp16-rounded)
__device__ float  d_x2[NFEAT];              // B2C * ||x~||^2

// ---------- PTX helpers ----------
__device__ __forceinline__ uint32_t smem_u32(const void* p) {
    uint32_t a;
    asm("{ .reg .u64 t; cvta.to.shared.u64 t, %1; cvt.u32.u64 %0, t; }"
        : "=r"(a) : "l"(p));
    return a;
}
__device__ __forceinline__ void cpa16(uint32_t dst, const void* src) {
    asm volatile("cp.async.cg.shared.global [%0], [%1], 16;"
                 :: "r"(dst), "l"(src));
}
#define CP_COMMIT() asm volatile("cp.async.commit_group;" ::: "memory")
#define CP_WAIT0()  asm volatile("cp.async.wait_group 0;" ::: "memory")

__device__ __forceinline__ void ldsm4(uint32_t* r, uint32_t addr) {
    asm volatile("ldmatrix.sync.aligned.m8n8.x4.shared.b16 {%0,%1,%2,%3}, [%4];"
                 : "=r"(r[0]), "=r"(r[1]), "=r"(r[2]), "=r"(r[3]) : "r"(addr));
}
__device__ __forceinline__ void ldsm4t(uint32_t* r, uint32_t addr) {
    asm volatile("ldmatrix.sync.aligned.m8n8.x4.trans.shared.b16 {%0,%1,%2,%3}, [%4];"
                 : "=r"(r[0]), "=r"(r[1]), "=r"(r[2]), "=r"(r[3]) : "r"(addr));
}
__device__ __forceinline__ void mma_f16(float* c, const uint32_t* a, const uint32_t* b) {
    asm volatile("mma.sync.aligned.m16n8k16.row.col.f32.f16.f16.f32 "
                 "{%0,%1,%2,%3}, {%4,%5,%6,%7}, {%8,%9}, {%0,%1,%2,%3};"
                 : "+f"(c[0]), "+f"(c[1]), "+f"(c[2]), "+f"(c[3])
                 : "r"(a[0]), "r"(a[1]), "r"(a[2]), "r"(a[3]), "r"(b[0]), "r"(b[1]));
}
__device__ __forceinline__ float fast_sqrt(float x) {
    float r; asm("sqrt.approx.f32 %0, %1;" : "=f"(r) : "f"(x)); return r;
}
__device__ __forceinline__ float fast_ex2(float x) {
    float r; asm("ex2.approx.f32 %0, %1;" : "=f"(r) : "f"(x)); return r;
}
__device__ __forceinline__ uint32_t pack_h2(float a, float b) {
    __half2 p = __floats2half2_rn(a, b);
    return *(uint32_t*)&p;
}

// ---------- prep kernels ----------
__global__ void zero_kernel(float* p, int n) {
    int i = blockIdx.x * blockDim.x + threadIdx.x;
    if (i < n) p[i] = 0.0f;
}

// rows -> fp16 + B2C-scaled norm of the rounded row. 8 warps/block, 1 row/warp.
__global__ void prep_rows(const float* __restrict__ src, __half* __restrict__ dst,
                          float* __restrict__ nrm, int nValid, int nTotal) {
    int r = blockIdx.x * 8 + (threadIdx.x >> 5);
    int lid = threadIdx.x & 31;
    if (r >= nTotal) return;
    float4 v = make_float4(0.f, 0.f, 0.f, 0.f);
    if (r < nValid) v = *(const float4*)(src + (size_t)r * DIM + lid * 4);
    uint32_t p0 = pack_h2(v.x, v.y), p1 = pack_h2(v.z, v.w);
    *(uint2*)(dst + (size_t)r * DIM + lid * 4) = make_uint2(p0, p1);
    float2 f0 = __half22float2(*(__half2*)&p0);
    float2 f1 = __half22float2(*(__half2*)&p1);
    float s = f0.x * f0.x + f0.y * f0.y + f1.x * f1.x + f1.y * f1.y;
    #pragma unroll
    for (int o = 16; o > 0; o >>= 1) s += __shfl_xor_sync(0xffffffffu, s, o);
    if (lid == 0) nrm[r] = s * B2C;
}

__global__ void prep_w(const float* __restrict__ src, __half* __restrict__ dst,
                       int nValid) {
    int idx = blockIdx.x * blockDim.x + threadIdx.x;   // one float4 each
    if (idx >= NPAD * OUTD / 4) return;
    int r = idx >> 4, c4 = idx & 15;
    float4 v = make_float4(0.f, 0.f, 0.f, 0.f);
    if (r < nValid) v = *(const float4*)(src + (size_t)r * OUTD + c4 * 4);
    *(uint2*)(dst + (size_t)r * OUTD + c4 * 4) =
        make_uint2(pack_h2(v.x, v.y), pack_h2(v.z, v.w));
}

// ---------- main fused kernel ----------
__global__ void __launch_bounds__(THREADS)
rbf_f16_kernel(float* __restrict__ out, int nChunks, int cps)
{
    extern __shared__ uint8_t sm[];
    uint32_t smb = smem_u32(sm);

    const int t = threadIdx.x, wid = t >> 5, lid = t & 31;
    const int qr = lid >> 2, qc = lid & 3;
    const int kh = wid & 1;          // k-half of the chunk (cols kh*64..)
    const int mb = wid >> 1;         // row band of 32

    const int rowBase = blockIdx.x * 128;
    const int chunk0  = blockIdx.y * cps;
    const int nc      = min(chunk0 + cps, nChunks) - chunk0;

    // cp.async index precompute
    const int tr = t >> 4, tc16 = t & 15;     // tile rows: tr, tr+16 x8
    const int wr = t >> 3, wc8 = t & 7;       // W rows: wr, wr+32 x4

    // ---- prologue: A + chunk0 tiles in one group ----
    #pragma unroll
    for (int i = 0; i < 8; i++)
        cpa16(smb + OFF_A + (uint32_t)(tr + i * 16) * TROWB + tc16 * 16,
              d_feat16 + (size_t)(rowBase + tr + i * 16) * DIM + tc16 * 8);
    {
        const int c0 = chunk0 * BC;
        #pragma unroll
        for (int i = 0; i < 8; i++)
            cpa16(smb + OFF_T + (uint32_t)(tr + i * 16) * TROWB + tc16 * 16,
                  d_train16 + (size_t)(c0 + tr + i * 16) * DIM + tc16 * 8);
        #pragma unroll
        for (int i = 0; i < 4; i++)
            cpa16(smb + OFF_W + (uint32_t)(wr + i * 32) * WROWB + wc8 * 16,
                  d_w16 + (size_t)(c0 + wr + i * 32) * OUTD + wc8 * 8);
        if (t < 32) cpa16(smb + OFF_T2 + t * 16, d_t2 + c0 + t * 4);
    }
    CP_COMMIT();

    // x2 (pre-scaled) for this warp's rows
    float x2v[2][2];
    #pragma unroll
    for (int mi = 0; mi < 2; mi++) {
        x2v[mi][0] = d_x2[rowBase + mb * 32 + mi * 16 + qr];
        x2v[mi][1] = d_x2[rowBase + mb * 32 + mi * 16 + qr + 8];
    }

    // fragment address helpers
    const int aRowL    = lid & 15;
    const int aColHalf = (lid >> 4) << 3;
    const int bRowOff  = ((lid >> 4) << 3) + (lid & 7);
    const int bColOff  = lid & 8;
    const int wKrow    = (((lid >> 3) & 1) << 3) + (lid & 7);
    const int wNcol    = (lid >> 4) << 3;

    float c2[2][8][4];
    #pragma unroll
    for (int mi = 0; mi < 2; mi++)
        #pragma unroll
        for (int nt = 0; nt < 8; nt++)
            #pragma unroll
            for (int q = 0; q < 4; q++) c2[mi][nt][q] = 0.f;

    CP_WAIT0();
    __syncthreads();

    for (int i = 0; i < nc; i++) {
        const int cur = i & 1, nxt = cur ^ 1;
        const uint32_t sTb = smb + OFF_T + cur * SZ_T;
        const uint32_t sWb = smb + OFF_W + cur * SZ_W;
        const float* sT2c = (const float*)(sm + OFF_T2 + cur * 512);

        // ---- issue prefetch of chunk i+1 into [nxt] ----
        if (i + 1 < nc) {
            const int c0 = (chunk0 + i + 1) * BC;
            #pragma unroll
            for (int j = 0; j < 8; j++)
                cpa16(smb + OFF_T + nxt * SZ_T
                          + (uint32_t)(tr + j * 16) * TROWB + tc16 * 16,
                      d_train16 + (size_t)(c0 + tr + j * 16) * DIM + tc16 * 8);
            #pragma unroll
            for (int j = 0; j < 4; j++)
                cpa16(smb + OFF_W + nxt * SZ_W
                          + (uint32_t)(wr + j * 32) * WROWB + wc8 * 16,
                      d_w16 + (size_t)(c0 + wr + j * 32) * OUTD + wc8 * 8);
            if (t < 32) cpa16(smb + OFF_T2 + nxt * 512 + t * 16, d_t2 + c0 + t * 4);
        }
        CP_COMMIT();

        // ---- GEMM1: c1 = A[mb*32.., :] @ T[kh*64.., :]^T  (32x64) ----
        float c1[2][8][4];
        #pragma unroll
        for (int mi = 0; mi < 2; mi++)
            #pragma unroll
            for (int nj = 0; nj < 8; nj++)
                #pragma unroll
                for (int q = 0; q < 4; q++) c1[mi][nj][q] = 0.f;

        #pragma unroll
        for (int ks = 0; ks < 8; ks++) {
            const int k0 = ks * 16;
            uint32_t a[2][4];
            #pragma unroll
            for (int mi = 0; mi < 2; mi++)
                ldsm4(a[mi], smb + OFF_A
                      + (uint32_t)(mb * 32 + mi * 16 + aRowL) * TROWB
                      + (uint32_t)(k0 + aColHalf) * 2);
            uint32_t b[8][2];
            #pragma unroll
            for (int p = 0; p < 4; p++) {
                uint32_t rr[4];
                ldsm4(rr, sTb
                      + (uint32_t)(kh * 64 + p * 16 + bRowOff) * TROWB
                      + (uint32_t)(k0 + bColOff) * 2);
                b[2 * p][0] = rr[0]; b[2 * p][1] = rr[1];
                b[2 * p + 1][0] = rr[2]; b[2 * p + 1][1] = rr[3];
            }
            #pragma unroll
            for (int mi = 0; mi < 2; mi++)
                #pragma unroll
                for (int nj = 0; nj < 8; nj++)
                    mma_f16(c1[mi][nj], a[mi], b[nj]);
        }

        // ---- per-16-col slice: epilogue -> A-frag -> GEMM2 ----
        #pragma unroll
        for (int s = 0; s < 4; s++) {
            const int cb = kh * 64 + s * 16;
            float2 t2a = *(float2*)&sT2c[cb + 2 * qc];
            float2 t2b = *(float2*)&sT2c[cb + 8 + 2 * qc];
            uint32_t ah[2][4];
            #pragma unroll
            for (int mi = 0; mi < 2; mi++) {
                float kk[2][4];
                #pragma unroll
                for (int half = 0; half < 2; half++) {
                    const float* cc = c1[mi][2 * s + half];
                    float2 t2p = half ? t2b : t2a;
                    #pragma unroll
                    for (int q = 0; q < 4; q++) {
                        float x2q = x2v[mi][q >> 1];
                        float tq  = (q & 1) ? t2p.y : t2p.x;
                        float d2  = fmaxf(fmaf(NEG2B2C, cc[q], x2q + tq), 0.f);
                        kk[half][q] = fast_ex2(-fast_sqrt(d2));
                    }
                }
                #pragma unroll
                for (int r = 0; r < 4; r++)
                    ah[mi][r] = pack_h2(kk[r >> 1][(r & 1) * 2],
                                        kk[r >> 1][(r & 1) * 2 + 1]);
            }

            const uint32_t wrow = (uint32_t)(kh * 64 + s * 16 + wKrow) * WROWB;
            #pragma unroll
            for (int u = 0; u < 4; u++) {
                uint32_t bh[4];
                ldsm4t(bh, sWb + wrow + (uint32_t)(u * 16 + wNcol) * 2);
                #pragma unroll
                for (int mi = 0; mi < 2; mi++)
                    #pragma unroll
                    for (int v = 0; v < 2; v++)
                        mma_f16(c2[mi][2 * u + v], ah[mi], &bh[2 * v]);
            }
        }

        CP_WAIT0();
        __syncthreads();   // next chunk data ready; [cur] free for rewrite
    }

    // ---- accumulate into global out (split over blockIdx.y and k-halves) ----
    #pragma unroll
    for (int mi = 0; mi < 2; mi++) {
        #pragma unroll
        for (int nt = 0; nt < 8; nt++) {
            int c = nt * 8 + 2 * qc;
            #pragma unroll
            for (int q = 0; q < 4; q++) {
                int r = rowBase + mb * 32 + mi * 16 + qr + ((q >> 1) << 3);
                atomicAdd(out + (size_t)r * OUTD + c + (q & 1), c2[mi][nt][q]);
            }
        }
    }
}

extern "C" void kernel_launch(void* const* d_in, const int* in_sizes, int n_in,
                              void* d_out, int out_size) {
    const float* features = (const float*)d_in[0];
    const float* train    = (const float*)d_in[1];
    const float* weights  = (const float*)d_in[2];
    float* out = (float*)d_out;

    int n = in_sizes[0] / DIM;    // 2048
    int N = in_sizes[1] / DIM;    // 50000

    int nChunks = (N + BC - 1) / BC;                 // 391
    int cps     = (nChunks + SPLITS - 1) / SPLITS;   // 44

    cudaFuncSetAttribute(rbf_f16_kernel,
                         cudaFuncAttributeMaxDynamicSharedMemorySize, SMEM_TOTAL);

    // resolve device-global addresses
    __half *p_train16, *p_w16, *p_feat16;
    float *p_t2, *p_x2;
    cudaGetSymbolAddress((void**)&p_train16, d_train16);
    cudaGetSymbolAddress((void**)&p_w16,     d_w16);
    cudaGetSymbolAddress((void**)&p_feat16,  d_feat16);
    cudaGetSymbolAddress((void**)&p_t2,      d_t2);
    cudaGetSymbolAddress((void**)&p_x2,      d_x2);

    int outN = n * OUTD;
    zero_kernel<<<(outN + 255) / 256, 256>>>(out, outN);
    prep_rows<<<NPAD / 8, 256>>>(train, p_train16, p_t2, N, NPAD);
    prep_rows<<<NFEAT / 8, 256>>>(features, p_feat16, p_x2, n, NFEAT);
    prep_w<<<(NPAD * OUTD / 4 + 255) / 256, 256>>>(weights, p_w16, N);

    dim3 grid(n / 128, SPLITS);
    rbf_f16_kernel<<<grid, THREADS, SMEM_TOTAL>>>(out, nChunks, cps);
}

// round 9
// speedup vs baseline: 16.7353x; 1.1547x over previous
#include <cuda_runtime.h>
#include <cuda_fp16.h>
#include <cstdint>

#define DIM 128
#define OUTD 64
#define BC 64
#define SPLITS 18
#define THREADS 256
#define NPAD 50048              // 782 * 64, padded train rows
#define NFEAT 2048

#define TSTRIDE 136             // fp16 per row of A/T tiles
#define TROWB   (TSTRIDE * 2)   // 272 B
#define WROWB   144             // W tile row bytes (72 halfs)

#define OFF_A   0
#define SZ_A    (128 * TROWB)             // 34816
#define OFF_T   (OFF_A + SZ_A)
#define SZ_T    (BC * TROWB)              // 17408 x2
#define OFF_W   (OFF_T + 2 * SZ_T)        // 69632
#define SZ_W    (BC * WROWB)              // 9216  x2
#define OFF_T2  (OFF_W + 2 * SZ_W)        // 88064, 2 x 512B
#define SMEM_TOTAL (OFF_T2 + 1024)        // 89088  -> 2 CTAs/SM

// k = exp(-dist/(2*RBF)) = 2^(-sqrt(d2p)), d2p = B2C*(x2 + t2 - 2 dot)
#define B2C ((float)((1.4426950408889634 / (2.0 * 10.077141124806595)) * \
                     (1.4426950408889634 / (2.0 * 10.077141124806595))))
#define NEG2B2C (-2.0f * B2C)

// ---- persistent device scratch ----
__device__ __half d_train16[NPAD * DIM];
__device__ __half d_w16[NPAD * OUTD];
__device__ __half d_feat16[NFEAT * DIM];
__device__ float  d_t2[NPAD];
__device__ float  d_x2[NFEAT];

// ---------- PTX helpers ----------
__device__ __forceinline__ uint32_t smem_u32(const void* p) {
    uint32_t a;
    asm("{ .reg .u64 t; cvta.to.shared.u64 t, %1; cvt.u32.u64 %0, t; }"
        : "=r"(a) : "l"(p));
    return a;
}
__device__ __forceinline__ void cpa16(uint32_t dst, const void* src) {
    asm volatile("cp.async.cg.shared.global [%0], [%1], 16;"
                 :: "r"(dst), "l"(src));
}
#define CP_COMMIT() asm volatile("cp.async.commit_group;" ::: "memory")
#define CP_WAIT0()  asm volatile("cp.async.wait_group 0;" ::: "memory")

__device__ __forceinline__ void ldsm4(uint32_t* r, uint32_t addr) {
    asm volatile("ldmatrix.sync.aligned.m8n8.x4.shared.b16 {%0,%1,%2,%3}, [%4];"
                 : "=r"(r[0]), "=r"(r[1]), "=r"(r[2]), "=r"(r[3]) : "r"(addr));
}
__device__ __forceinline__ void ldsm4t(uint32_t* r, uint32_t addr) {
    asm volatile("ldmatrix.sync.aligned.m8n8.x4.trans.shared.b16 {%0,%1,%2,%3}, [%4];"
                 : "=r"(r[0]), "=r"(r[1]), "=r"(r[2]), "=r"(r[3]) : "r"(addr));
}
__device__ __forceinline__ void mma_f16(float* c, const uint32_t* a, const uint32_t* b) {
    asm volatile("mma.sync.aligned.m16n8k16.row.col.f32.f16.f16.f32 "
                 "{%0,%1,%2,%3}, {%4,%5,%6,%7}, {%8,%9}, {%0,%1,%2,%3};"
                 : "+f"(c[0]), "+f"(c[1]), "+f"(c[2]), "+f"(c[3])
                 : "r"(a[0]), "r"(a[1]), "r"(a[2]), "r"(a[3]), "r"(b[0]), "r"(b[1]));
}
__device__ __forceinline__ float fast_sqrt(float x) {
    float r; asm("sqrt.approx.f32 %0, %1;" : "=f"(r) : "f"(x)); return r;
}
__device__ __forceinline__ float fast_ex2(float x) {
    float r; asm("ex2.approx.f32 %0, %1;" : "=f"(r) : "f"(x)); return r;
}
__device__ __forceinline__ uint32_t pack_h2(float a, float b) {
    __half2 p = __floats2half2_rn(a, b);
    return *(uint32_t*)&p;
}

// ---------- prep kernels ----------
__global__ void zero_kernel(float* p, int n) {
    int i = blockIdx.x * blockDim.x + threadIdx.x;
    if (i < n) p[i] = 0.0f;
}

__global__ void prep_rows(const float* __restrict__ src, __half* __restrict__ dst,
                          float* __restrict__ nrm, int nValid, int nTotal) {
    int r = blockIdx.x * 8 + (threadIdx.x >> 5);
    int lid = threadIdx.x & 31;
    if (r >= nTotal) return;
    float4 v = make_float4(0.f, 0.f, 0.f, 0.f);
    if (r < nValid) v = *(const float4*)(src + (size_t)r * DIM + lid * 4);
    uint32_t p0 = pack_h2(v.x, v.y), p1 = pack_h2(v.z, v.w);
    *(uint2*)(dst + (size_t)r * DIM + lid * 4) = make_uint2(p0, p1);
    float2 f0 = __half22float2(*(__half2*)&p0);
    float2 f1 = __half22float2(*(__half2*)&p1);
    float s = f0.x * f0.x + f0.y * f0.y + f1.x * f1.x + f1.y * f1.y;
    #pragma unroll
    for (int o = 16; o > 0; o >>= 1) s += __shfl_xor_sync(0xffffffffu, s, o);
    if (lid == 0) nrm[r] = s * B2C;
}

__global__ void prep_w(const float* __restrict__ src, __half* __restrict__ dst,
                       int nValid) {
    int idx = blockIdx.x * blockDim.x + threadIdx.x;
    if (idx >= NPAD * OUTD / 4) return;
    int r = idx >> 4, c4 = idx & 15;
    float4 v = make_float4(0.f, 0.f, 0.f, 0.f);
    if (r < nValid) v = *(const float4*)(src + (size_t)r * OUTD + c4 * 4);
    *(uint2*)(dst + (size_t)r * OUTD + c4 * 4) =
        make_uint2(pack_h2(v.x, v.y), pack_h2(v.z, v.w));
}

// ---------- main fused kernel ----------
__global__ void __launch_bounds__(THREADS, 2)
rbf_f16_kernel(float* __restrict__ out, int nChunks, int cps)
{
    extern __shared__ uint8_t sm[];
    uint32_t smb = smem_u32(sm);

    const int t = threadIdx.x, wid = t >> 5, lid = t & 31;
    const int qr = lid >> 2, qc = lid & 3;
    const int mb = wid;              // row band of 16: rows mb*16..

    const int rowBase = blockIdx.x * 128;
    const int chunk0  = blockIdx.y * cps;
    const int nc      = min(chunk0 + cps, nChunks) - chunk0;

    // cp.async index precompute
    const int tr = t >> 4, tc16 = t & 15;     // T rows: tr + i*16 (i<4)
    const int wr = t >> 3, wc8 = t & 7;       // W rows: wr + i*32 (i<2)

    // ---- prologue: A + chunk0 tiles in one group ----
    #pragma unroll
    for (int i = 0; i < 8; i++)
        cpa16(smb + OFF_A + (uint32_t)(tr + i * 16) * TROWB + tc16 * 16,
              d_feat16 + (size_t)(rowBase + tr + i * 16) * DIM + tc16 * 8);
    {
        const int c0 = chunk0 * BC;
        #pragma unroll
        for (int i = 0; i < 4; i++)
            cpa16(smb + OFF_T + (uint32_t)(tr + i * 16) * TROWB + tc16 * 16,
                  d_train16 + (size_t)(c0 + tr + i * 16) * DIM + tc16 * 8);
        #pragma unroll
        for (int i = 0; i < 2; i++)
            cpa16(smb + OFF_W + (uint32_t)(wr + i * 32) * WROWB + wc8 * 16,
                  d_w16 + (size_t)(c0 + wr + i * 32) * OUTD + wc8 * 8);
        if (t < 16) cpa16(smb + OFF_T2 + t * 16, d_t2 + c0 + t * 4);
    }
    CP_COMMIT();

    // x2 (pre-scaled) for this warp's rows
    const float x2lo = d_x2[rowBase + mb * 16 + qr];
    const float x2hi = d_x2[rowBase + mb * 16 + qr + 8];

    // fragment address helpers
    const int aRowL    = lid & 15;
    const int aColHalf = (lid >> 4) << 3;
    const int bRowOff  = ((lid >> 4) << 3) + (lid & 7);
    const int bColOff  = lid & 8;
    const int wKrow    = (((lid >> 3) & 1) << 3) + (lid & 7);
    const int wNcol    = (lid >> 4) << 3;

    float c2[8][4];
    #pragma unroll
    for (int nt = 0; nt < 8; nt++)
        #pragma unroll
        for (int q = 0; q < 4; q++) c2[nt][q] = 0.f;

    CP_WAIT0();
    __syncthreads();

    for (int i = 0; i < nc; i++) {
        const int cur = i & 1, nxt = cur ^ 1;
        const uint32_t sTb = smb + OFF_T + cur * SZ_T;
        const uint32_t sWb = smb + OFF_W + cur * SZ_W;
        const float* sT2c = (const float*)(sm + OFF_T2 + cur * 512);

        // ---- issue prefetch of chunk i+1 into [nxt] ----
        if (i + 1 < nc) {
            const int c0 = (chunk0 + i + 1) * BC;
            #pragma unroll
            for (int j = 0; j < 4; j++)
                cpa16(smb + OFF_T + nxt * SZ_T
                          + (uint32_t)(tr + j * 16) * TROWB + tc16 * 16,
                      d_train16 + (size_t)(c0 + tr + j * 16) * DIM + tc16 * 8);
            #pragma unroll
            for (int j = 0; j < 2; j++)
                cpa16(smb + OFF_W + nxt * SZ_W
                          + (uint32_t)(wr + j * 32) * WROWB + wc8 * 16,
                      d_w16 + (size_t)(c0 + wr + j * 32) * OUTD + wc8 * 8);
            if (t < 16) cpa16(smb + OFF_T2 + nxt * 512 + t * 16, d_t2 + c0 + t * 4);
        }
        CP_COMMIT();

        // ---- GEMM1: c1 = A[mb*16.., :] @ T^T  (16 x 64) ----
        float c1[8][4];
        #pragma unroll
        for (int nj = 0; nj < 8; nj++)
            #pragma unroll
            for (int q = 0; q < 4; q++) c1[nj][q] = 0.f;

        #pragma unroll
        for (int ks = 0; ks < 8; ks++) {
            const int k0 = ks * 16;
            uint32_t a[4];
            ldsm4(a, smb + OFF_A
                  + (uint32_t)(mb * 16 + aRowL) * TROWB
                  + (uint32_t)(k0 + aColHalf) * 2);
            #pragma unroll
            for (int p = 0; p < 4; p++) {
                uint32_t rr[4];
                ldsm4(rr, sTb
                      + (uint32_t)(p * 16 + bRowOff) * TROWB
                      + (uint32_t)(k0 + bColOff) * 2);
                mma_f16(c1[2 * p],     a, &rr[0]);
                mma_f16(c1[2 * p + 1], a, &rr[2]);
            }
        }

        // ---- per-16-col slice: epilogue -> A-frag -> GEMM2 ----
        #pragma unroll
        for (int s = 0; s < 4; s++) {
            const int cb = s * 16;
            float2 t2a = *(float2*)&sT2c[cb + 2 * qc];
            float2 t2b = *(float2*)&sT2c[cb + 8 + 2 * qc];
            float kk[2][4];
            #pragma unroll
            for (int half = 0; half < 2; half++) {
                const float* cc = c1[2 * s + half];
                float2 t2p = half ? t2b : t2a;
                #pragma unroll
                for (int q = 0; q < 4; q++) {
                    float x2q = (q >> 1) ? x2hi : x2lo;
                    float tq  = (q & 1) ? t2p.y : t2p.x;
                    float d2  = fmaxf(fmaf(NEG2B2C, cc[q], x2q + tq), 0.f);
                    kk[half][q] = fast_ex2(-fast_sqrt(d2));
                }
            }
            uint32_t ah[4];
            #pragma unroll
            for (int r = 0; r < 4; r++)
                ah[r] = pack_h2(kk[r >> 1][(r & 1) * 2],
                                kk[r >> 1][(r & 1) * 2 + 1]);

            const uint32_t wrow = (uint32_t)(s * 16 + wKrow) * WROWB;
            #pragma unroll
            for (int u = 0; u < 4; u++) {
                uint32_t bh[4];
                ldsm4t(bh, sWb + wrow + (uint32_t)(u * 16 + wNcol) * 2);
                mma_f16(c2[2 * u],     ah, &bh[0]);
                mma_f16(c2[2 * u + 1], ah, &bh[2]);
            }
        }

        CP_WAIT0();
        __syncthreads();   // next chunk data ready; [cur] free for rewrite
    }

    // ---- accumulate into global out (split over blockIdx.y) ----
    #pragma unroll
    for (int nt = 0; nt < 8; nt++) {
        int c = nt * 8 + 2 * qc;
        #pragma unroll
        for (int q = 0; q < 4; q++) {
            int r = rowBase + mb * 16 + qr + ((q >> 1) << 3);
            atomicAdd(out + (size_t)r * OUTD + c + (q & 1), c2[nt][q]);
        }
    }
}

extern "C" void kernel_launch(void* const* d_in, const int* in_sizes, int n_in,
                              void* d_out, int out_size) {
    const float* features = (const float*)d_in[0];
    const float* train    = (const float*)d_in[1];
    const float* weights  = (const float*)d_in[2];
    float* out = (float*)d_out;

    int n = in_sizes[0] / DIM;    // 2048
    int N = in_sizes[1] / DIM;    // 50000

    int nChunks = (N + BC - 1) / BC;                 // 782
    int cps     = (nChunks + SPLITS - 1) / SPLITS;   // 44

    cudaFuncSetAttribute(rbf_f16_kernel,
                         cudaFuncAttributeMaxDynamicSharedMemorySize, SMEM_TOTAL);

    __half *p_train16, *p_w16, *p_feat16;
    float *p_t2, *p_x2;
    cudaGetSymbolAddress((void**)&p_train16, d_train16);
    cudaGetSymbolAddress((void**)&p_w16,     d_w16);
    cudaGetSymbolAddress((void**)&p_feat16,  d_feat16);
    cudaGetSymbolAddress((void**)&p_t2,      d_t2);
    cudaGetSymbolAddress((void**)&p_x2,      d_x2);

    int outN = n * OUTD;
    zero_kernel<<<(outN + 255) / 256, 256>>>(out, outN);
    prep_rows<<<NPAD / 8, 256>>>(train, p_train16, p_t2, N, NPAD);
    prep_rows<<<NFEAT / 8, 256>>>(features, p_feat16, p_x2, n, NFEAT);
    prep_w<<<(NPAD * OUTD / 4 + 255) / 256, 256>>>(weights, p_w16, N);

    dim3 grid(n / 128, SPLITS);
    rbf_f16_kernel<<<grid, THREADS, SMEM_TOTAL>>>(out, nChunks, cps);
}